// round 9
// baseline (speedup 1.0000x reference)
#include <cuda_runtime.h>
#include <math.h>
#include <stdint.h>

#define NUM_CLASSES 1000000
#define DIMK 64
#define BATCHN 4096
#define NS 1024

typedef unsigned long long ull;

// Scratch (device globals: allocation-free per harness rules)
__device__ float g_ST[DIMK * NS];      // gathered sampled weights, d-major [64][1024]
__device__ float g_slq[NS];            // samp_log_q
__device__ float g_tlq[BATCHN];        // true_log_q
__device__ float g_tl[BATCHN];         // raw true dot products

// ---------------------------------------------------------------------------
// PROVEN reference-log (R8, rel_err 5.7e-8): XLA:CPU GenerateVF32Log —
// Cephes constants, q1/q2 split ln2, Estrin 3-chain, ALL mul/adds unfused,
// old-Eigen tail order. DO NOT MODIFY.
// ---------------------------------------------------------------------------
__device__ __forceinline__ float xla_logf(float xx) {
    uint32_t ib = __float_as_uint(xx);
    float e = __fadd_rn((float)((int)(ib >> 23) - 0x7f), 1.0f);
    float x = __uint_as_float((ib & 0x007fffffu) | 0x3f000000u);  // [0.5, 1)
    bool mask = x < 0.707106781186547524f;
    float tmp = mask ? x : 0.0f;
    x = __fadd_rn(x, -1.0f);
    e = __fadd_rn(e, mask ? -1.0f : 0.0f);
    x = __fadd_rn(x, tmp);

    float x2 = __fmul_rn(x, x);
    float x3 = __fmul_rn(x2, x);

    float y  = __fadd_rn(__fmul_rn(7.0376836292E-2f, x), -1.1514610310E-1f);
    float y1 = __fadd_rn(__fmul_rn(-1.2420140846E-1f, x), 1.4249322787E-1f);
    float y2 = __fadd_rn(__fmul_rn(2.0000714765E-1f, x), -2.4999993993E-1f);
    y  = __fadd_rn(__fmul_rn(y, x), 1.1676998740E-1f);
    y1 = __fadd_rn(__fmul_rn(y1, x), -1.6668057665E-1f);
    y2 = __fadd_rn(__fmul_rn(y2, x), 3.3333331174E-1f);
    y  = __fadd_rn(__fmul_rn(y, x3), y1);
    y  = __fadd_rn(__fmul_rn(y, x3), y2);
    y  = __fmul_rn(y, x3);

    float t1 = __fmul_rn(e, -2.12194440e-4f);
    float t2 = __fmul_rn(x2, 0.5f);
    y = __fadd_rn(y, t1);
    x = __fadd_rn(x, -t2);
    float t3 = __fmul_rn(e, 0.693359375f);
    x = __fadd_rn(x, y);
    x = __fadd_rn(x, t3);
    return x;
}

__device__ __forceinline__ float log_q_of(int c) {
    float cf = (float)c;
    float l2 = xla_logf(__fadd_rn(cf, 2.0f));
    float l1 = xla_logf(__fadd_rn(cf, 1.0f));
    float lnc = xla_logf(1000001.0f);
    float p = __fdiv_rn(__fadd_rn(l2, -l1), lnc);
    float np = __fmul_rn(1024.0f, p);
    return xla_logf(np);
}

// ---- packed f32x2 helpers (sm_100+) ----
__device__ __forceinline__ ull pk2(float v) {
    ull r; asm("mov.b64 %0, {%1, %1};" : "=l"(r) : "f"(v)); return r;
}
__device__ __forceinline__ ull fma2(ull a, ull b, ull c) {
    ull d; asm("fma.rn.f32x2 %0, %1, %2, %3;" : "=l"(d) : "l"(a), "l"(b), "l"(c)); return d;
}
__device__ __forceinline__ float2 up2(ull v) {
    float2 f; asm("mov.b64 {%0, %1}, %2;" : "=f"(f.x), "=f"(f.y) : "l"(v)); return f;
}

// K1: blocks 0..255: gather sampled columns + log-q's (identical to R8).
//     blocks 256..767: one warp per batch row: raw true dot -> g_tl.
__global__ void __launch_bounds__(256) prep_kernel(
    const float* __restrict__ item,
    const float* __restrict__ user,
    const int*   __restrict__ labels,
    const int*   __restrict__ sid)
{
    int bid = blockIdx.x;
    int tid = (int)threadIdx.x;
    if (bid < 256) {
        int idx = bid * 256 + tid;                    // 0 .. 65535
        int d = idx >> 10;
        int j = idx & 1023;
        int c = sid[j];
        g_ST[idx] = item[(size_t)d * NUM_CLASSES + (size_t)c];
        if (idx < NS)     g_slq[idx] = log_q_of(sid[idx]);
        if (idx < BATCHN) g_tlq[idx] = log_q_of(labels[idx]);
    } else {
        int lane = tid & 31;
        int b = (bid - 256) * 8 + (tid >> 5);
        int lab = labels[b];
        float td = user[(size_t)lane * BATCHN + b]        * item[(size_t)lane        * NUM_CLASSES + lab]
                 + user[(size_t)(lane + 32) * BATCHN + b] * item[(size_t)(lane + 32) * NUM_CLASSES + lab];
        #pragma unroll
        for (int o = 16; o; o >>= 1) td += __shfl_xor_sync(0xffffffffu, td, o);
        if (lane == 0) g_tl[b] = td;
    }
}

// K2: fused GEMM + online softmax + loss. Block = 16 batch rows, streams the
// 1024 sampled cols in 4 tiles of 256. Micro-tile 2 rows x 8 cols as f32x2
// pairs (fma.rn.f32x2 = 2 IEEE FMAs/inst, same accumulation order as R8).
__global__ void __launch_bounds__(256, 2) fused_kernel(
    const float* __restrict__ user,
    const int*   __restrict__ labels,
    const int*   __restrict__ sid,
    float*       __restrict__ out)
{
    extern __shared__ float Ss[];        // [64][256] = 64KB (dynamic)
    __shared__ float Us[DIMK][16];       // U tile, [d][row]
    __shared__ float slq_s[NS];
    __shared__ int   sid_s[NS];
    __shared__ int   lab_s[16];

    int tid = (int)threadIdx.x;
    int b0 = blockIdx.x * 16;

    for (int t = tid; t < NS; t += 256) { slq_s[t] = g_slq[t]; sid_s[t] = sid[t]; }
    for (int t = tid; t < DIMK * 16; t += 256) {
        int d = t >> 4, r = t & 15;
        Us[d][r] = user[(size_t)d * BATCHN + b0 + r];
    }
    if (tid < 16) lab_s[tid] = labels[b0 + tid];
    __syncthreads();

    int rowg = tid >> 5;           // 0..7  (warp id)
    int colg = tid & 31;           // 0..31 (lane id)
    int r0 = rowg * 2;
    int lab0 = lab_s[r0], lab1 = lab_s[r0 + 1];

    float m0 = -1e30f, m1 = -1e30f, s0 = 0.0f, s1 = 0.0f;

    for (int t = 0; t < 4; t++) {
        int j0 = t * 256;
        // Load ST tile [64][256] from g_ST (L2-resident after first wave)
        for (int u = tid; u < 64 * 64; u += 256) {       // float4 units
            int d = u >> 6, x = (u & 63) << 2;
            *(float4*)&Ss[d * 256 + x] = *(const float4*)&g_ST[d * NS + j0 + x];
        }
        __syncthreads();

        ull a00 = 0, a01 = 0, a02 = 0, a03 = 0;   // row r0, col pairs p=0..3
        ull a10 = 0, a11 = 0, a12 = 0, a13 = 0;   // row r0+1
        #pragma unroll 16
        for (int d = 0; d < DIMK; d++) {
            const float* sr = &Ss[d * 256];
            ull pa0 = pk2(Us[d][r0]);
            ull pa1 = pk2(Us[d][r0 + 1]);
            ull b0p = *(const ull*)&sr[2 * colg];
            ull b1p = *(const ull*)&sr[2 * colg + 64];
            ull b2p = *(const ull*)&sr[2 * colg + 128];
            ull b3p = *(const ull*)&sr[2 * colg + 192];
            a00 = fma2(pa0, b0p, a00);  a10 = fma2(pa1, b0p, a10);
            a01 = fma2(pa0, b1p, a01);  a11 = fma2(pa1, b1p, a11);
            a02 = fma2(pa0, b2p, a02);  a12 = fma2(pa1, b2p, a12);
            a03 = fma2(pa0, b3p, a03);  a13 = fma2(pa1, b3p, a13);
        }
        __syncthreads();   // done reading Ss; epilogue is register-only

        // Epilogue: logits, mask, online max/sum (per-thread, per row)
        float2 v0[4] = { up2(a00), up2(a01), up2(a02), up2(a03) };
        float2 v1[4] = { up2(a10), up2(a11), up2(a12), up2(a13) };
        float w0[8], w1[8];
        #pragma unroll
        for (int p = 0; p < 4; p++) {
            int jl = j0 + 2 * colg + 64 * p;
            float q0 = slq_s[jl], q1 = slq_s[jl + 1];
            int i0 = sid_s[jl], i1 = sid_s[jl + 1];
            w0[2*p]   = v0[p].x - q0 - (i0 == lab0 ? 1000000000.0f : 0.0f);
            w0[2*p+1] = v0[p].y - q1 - (i1 == lab0 ? 1000000000.0f : 0.0f);
            w1[2*p]   = v1[p].x - q0 - (i0 == lab1 ? 1000000000.0f : 0.0f);
            w1[2*p+1] = v1[p].y - q1 - (i1 == lab1 ? 1000000000.0f : 0.0f);
        }
        float lm0 = w0[0], lm1 = w1[0];
        #pragma unroll
        for (int k = 1; k < 8; k++) { lm0 = fmaxf(lm0, w0[k]); lm1 = fmaxf(lm1, w1[k]); }
        float mn0 = fmaxf(m0, lm0), mn1 = fmaxf(m1, lm1);
        float acc0 = s0 * __expf(m0 - mn0);
        float acc1 = s1 * __expf(m1 - mn1);
        #pragma unroll
        for (int k = 0; k < 8; k++) {
            acc0 += __expf(w0[k] - mn0);
            acc1 += __expf(w1[k] - mn1);
        }
        s0 = acc0; m0 = mn0;
        s1 = acc1; m1 = mn1;
    }

    // Combine (m,s) across the 32 lanes of this warp (each lane = 8 cols/tile)
    #pragma unroll
    for (int o = 16; o; o >>= 1) {
        float om = __shfl_xor_sync(0xffffffffu, m0, o);
        float os = __shfl_xor_sync(0xffffffffu, s0, o);
        float mn = fmaxf(m0, om);
        s0 = s0 * __expf(m0 - mn) + os * __expf(om - mn);
        m0 = mn;
        om = __shfl_xor_sync(0xffffffffu, m1, o);
        os = __shfl_xor_sync(0xffffffffu, s1, o);
        mn = fmaxf(m1, om);
        s1 = s1 * __expf(m1 - mn) + os * __expf(om - mn);
        m1 = mn;
    }

    if (colg == 0) {
        int b = b0 + r0;
        float tl = g_tl[b] - g_tlq[b];
        float mn = fmaxf(m0, tl);
        float st = s0 * __expf(m0 - mn) + __expf(tl - mn);
        out[b] = mn + xla_logf(st) - tl;

        b = b0 + r0 + 1;
        tl = g_tl[b] - g_tlq[b];
        mn = fmaxf(m1, tl);
        st = s1 * __expf(m1 - mn) + __expf(tl - mn);
        out[b] = mn + xla_logf(st) - tl;
    }
}

extern "C" void kernel_launch(void* const* d_in, const int* in_sizes, int n_in,
                              void* d_out, int out_size)
{
    const float* item = (const float*)d_in[0];   // [64, 1000000]
    const float* user = (const float*)d_in[1];   // [64, 4096]
    const int*   lab  = (const int*)  d_in[2];   // [4096, 1]
    const int*   sid  = (const int*)  d_in[3];   // [1024]
    float*       out  = (float*)d_out;           // [4096, 1]

    static int smem_set = 0;
    if (!smem_set) {
        cudaFuncSetAttribute(fused_kernel,
                             cudaFuncAttributeMaxDynamicSharedMemorySize, 65536);
        smem_set = 1;
    }

    prep_kernel<<<768, 256>>>(item, user, lab, sid);
    fused_kernel<<<256, 256, 65536>>>(user, lab, sid, out);
}

// round 10
// speedup vs baseline: 1.1296x; 1.1296x over previous
#include <cuda_runtime.h>
#include <math.h>
#include <stdint.h>

#define NUM_CLASSES 1000000
#define DIMK 64
#define BATCHN 4096
#define NS 1024
#define TC 256         // cols per streamed tile
#define RPB 32         // batch rows per block

typedef unsigned long long ull;

// Scratch (device globals: allocation-free per harness rules)
__device__ float g_ST[DIMK * NS];      // gathered sampled weights, d-major [64][1024]
__device__ float g_slq[NS];            // samp_log_q
__device__ float g_tlq[BATCHN];        // true_log_q
__device__ float g_tl[BATCHN];         // raw true dot products

// ---------------------------------------------------------------------------
// PROVEN reference-log (R8, rel_err 5.7e-8): XLA:CPU GenerateVF32Log —
// Cephes constants, q1/q2 split ln2, Estrin 3-chain, ALL mul/adds unfused,
// old-Eigen tail order. DO NOT MODIFY.
// ---------------------------------------------------------------------------
__device__ __forceinline__ float xla_logf(float xx) {
    uint32_t ib = __float_as_uint(xx);
    float e = __fadd_rn((float)((int)(ib >> 23) - 0x7f), 1.0f);
    float x = __uint_as_float((ib & 0x007fffffu) | 0x3f000000u);  // [0.5, 1)
    bool mask = x < 0.707106781186547524f;
    float tmp = mask ? x : 0.0f;
    x = __fadd_rn(x, -1.0f);
    e = __fadd_rn(e, mask ? -1.0f : 0.0f);
    x = __fadd_rn(x, tmp);

    float x2 = __fmul_rn(x, x);
    float x3 = __fmul_rn(x2, x);

    float y  = __fadd_rn(__fmul_rn(7.0376836292E-2f, x), -1.1514610310E-1f);
    float y1 = __fadd_rn(__fmul_rn(-1.2420140846E-1f, x), 1.4249322787E-1f);
    float y2 = __fadd_rn(__fmul_rn(2.0000714765E-1f, x), -2.4999993993E-1f);
    y  = __fadd_rn(__fmul_rn(y, x), 1.1676998740E-1f);
    y1 = __fadd_rn(__fmul_rn(y1, x), -1.6668057665E-1f);
    y2 = __fadd_rn(__fmul_rn(y2, x), 3.3333331174E-1f);
    y  = __fadd_rn(__fmul_rn(y, x3), y1);
    y  = __fadd_rn(__fmul_rn(y, x3), y2);
    y  = __fmul_rn(y, x3);

    float t1 = __fmul_rn(e, -2.12194440e-4f);
    float t2 = __fmul_rn(x2, 0.5f);
    y = __fadd_rn(y, t1);
    x = __fadd_rn(x, -t2);
    float t3 = __fmul_rn(e, 0.693359375f);
    x = __fadd_rn(x, y);
    x = __fadd_rn(x, t3);
    return x;
}

__device__ __forceinline__ float log_q_of(int c) {
    float cf = (float)c;
    float l2 = xla_logf(__fadd_rn(cf, 2.0f));
    float l1 = xla_logf(__fadd_rn(cf, 1.0f));
    float lnc = xla_logf(1000001.0f);
    float p = __fdiv_rn(__fadd_rn(l2, -l1), lnc);
    float np = __fmul_rn(1024.0f, p);
    return xla_logf(np);
}

// ---- packed f32x2 helpers (sm_100+) ----
__device__ __forceinline__ ull pk2(float v) {
    ull r; asm("mov.b64 %0, {%1, %1};" : "=l"(r) : "f"(v)); return r;
}
__device__ __forceinline__ ull fma2(ull a, ull b, ull c) {
    ull d; asm("fma.rn.f32x2 %0, %1, %2, %3;" : "=l"(d) : "l"(a), "l"(b), "l"(c)); return d;
}
__device__ __forceinline__ float2 up2(ull v) {
    float2 f; asm("mov.b64 {%0, %1}, %2;" : "=f"(f.x), "=f"(f.y) : "l"(v)); return f;
}

// K1: blocks 0..255: gather sampled columns + log-q's.
//     blocks 256..767: one warp per batch row: raw true dot -> g_tl.
__global__ void __launch_bounds__(256) prep_kernel(
    const float* __restrict__ item,
    const float* __restrict__ user,
    const int*   __restrict__ labels,
    const int*   __restrict__ sid)
{
    int bid = blockIdx.x;
    int tid = (int)threadIdx.x;
    if (bid < 256) {
        int idx = bid * 256 + tid;                    // 0 .. 65535
        int d = idx >> 10;
        int j = idx & 1023;
        int c = sid[j];
        g_ST[idx] = item[(size_t)d * NUM_CLASSES + (size_t)c];
        if (idx < NS)     g_slq[idx] = log_q_of(sid[idx]);
        if (idx < BATCHN) g_tlq[idx] = log_q_of(labels[idx]);
    } else {
        int lane = tid & 31;
        int b = (bid - 256) * 8 + (tid >> 5);
        int lab = labels[b];
        float td = user[(size_t)lane * BATCHN + b]        * item[(size_t)lane        * NUM_CLASSES + lab]
                 + user[(size_t)(lane + 32) * BATCHN + b] * item[(size_t)(lane + 32) * NUM_CLASSES + lab];
        #pragma unroll
        for (int o = 16; o; o >>= 1) td += __shfl_xor_sync(0xffffffffu, td, o);
        if (lane == 0) g_tl[b] = td;
    }
}

// K2: fused GEMM + online softmax + loss. Block = 32 batch rows (8 warps x 4),
// streams the 1024 cols in 4 tiles of 256. Micro-tile 4 rows x 8 cols as
// f32x2 pairs: per d-step 32 lane-FMAs per 32B of B smem traffic (2x R9).
__global__ void __launch_bounds__(256, 2) fused_kernel(
    const float* __restrict__ user,
    const int*   __restrict__ labels,
    const int*   __restrict__ sid,
    float*       __restrict__ out)
{
    extern __shared__ float Ss[];        // [64][TC] = 64KB (dynamic)
    __shared__ float Us[DIMK][RPB];      // A tile [d][row], 8KB
    __shared__ float slq_s[NS];
    __shared__ int   sid_s[NS];
    __shared__ int   lab_s[RPB];

    int tid = (int)threadIdx.x;
    int b0 = blockIdx.x * RPB;

    for (int t = tid; t < NS; t += 256) { slq_s[t] = g_slq[t]; sid_s[t] = sid[t]; }
    for (int t = tid; t < DIMK * RPB; t += 256) {
        int d = t >> 5, r = t & 31;
        Us[d][r] = user[(size_t)d * BATCHN + b0 + r];
    }
    if (tid < RPB) lab_s[tid] = labels[b0 + tid];
    __syncthreads();

    int wid = tid >> 5;            // 0..7
    int l = tid & 31;              // lane
    int r0 = wid * 4;              // 4 rows per warp

    int labr[4];
    float m[4], s[4];
    #pragma unroll
    for (int i = 0; i < 4; i++) { labr[i] = lab_s[r0 + i]; m[i] = -1e30f; s[i] = 0.0f; }

    for (int t = 0; t < 4; t++) {
        int j0 = t * TC;
        // Stage B tile [64][TC] from g_ST (L2-resident)
        for (int u = tid; u < DIMK * (TC / 4); u += 256) {
            int d = u / (TC / 4), x = (u % (TC / 4)) << 2;
            *(float4*)&Ss[d * TC + x] = *(const float4*)&g_ST[d * NS + j0 + x];
        }
        __syncthreads();

        ull acc[4][4];
        #pragma unroll
        for (int i = 0; i < 4; i++)
            #pragma unroll
            for (int p = 0; p < 4; p++) acc[i][p] = 0;

        #pragma unroll 8
        for (int d = 0; d < DIMK; d++) {
            const float* sr = &Ss[d * TC];
            ull bp0 = *(const ull*)&sr[2 * l];
            ull bp1 = *(const ull*)&sr[2 * l + 64];
            ull bp2 = *(const ull*)&sr[2 * l + 128];
            ull bp3 = *(const ull*)&sr[2 * l + 192];
            float4 av = *(const float4*)&Us[d][r0];
            ull a0 = pk2(av.x), a1 = pk2(av.y), a2 = pk2(av.z), a3 = pk2(av.w);
            acc[0][0] = fma2(a0, bp0, acc[0][0]);
            acc[1][0] = fma2(a1, bp0, acc[1][0]);
            acc[2][0] = fma2(a2, bp0, acc[2][0]);
            acc[3][0] = fma2(a3, bp0, acc[3][0]);
            acc[0][1] = fma2(a0, bp1, acc[0][1]);
            acc[1][1] = fma2(a1, bp1, acc[1][1]);
            acc[2][1] = fma2(a2, bp1, acc[2][1]);
            acc[3][1] = fma2(a3, bp1, acc[3][1]);
            acc[0][2] = fma2(a0, bp2, acc[0][2]);
            acc[1][2] = fma2(a1, bp2, acc[1][2]);
            acc[2][2] = fma2(a2, bp2, acc[2][2]);
            acc[3][2] = fma2(a3, bp2, acc[3][2]);
            acc[0][3] = fma2(a0, bp3, acc[0][3]);
            acc[1][3] = fma2(a1, bp3, acc[1][3]);
            acc[2][3] = fma2(a2, bp3, acc[2][3]);
            acc[3][3] = fma2(a3, bp3, acc[3][3]);
        }
        __syncthreads();   // done reading Ss before next tile overwrite

        // Epilogue per row: logits, mask, online max/sum
        #pragma unroll
        for (int i = 0; i < 4; i++) {
            float w[8];
            #pragma unroll
            for (int p = 0; p < 4; p++) {
                float2 v = up2(acc[i][p]);
                int jl = j0 + 2 * l + 64 * p;
                w[2*p]   = v.x - slq_s[jl]     - (sid_s[jl]     == labr[i] ? 1000000000.0f : 0.0f);
                w[2*p+1] = v.y - slq_s[jl + 1] - (sid_s[jl + 1] == labr[i] ? 1000000000.0f : 0.0f);
            }
            float lm = w[0];
            #pragma unroll
            for (int k = 1; k < 8; k++) lm = fmaxf(lm, w[k]);
            float mn = fmaxf(m[i], lm);
            float acc_s = s[i] * __expf(m[i] - mn);
            #pragma unroll
            for (int k = 0; k < 8; k++) acc_s += __expf(w[k] - mn);
            s[i] = acc_s; m[i] = mn;
        }
    }

    // Combine (m,s) across the 32 lanes, per row
    #pragma unroll
    for (int i = 0; i < 4; i++) {
        float mi = m[i], si = s[i];
        #pragma unroll
        for (int o = 16; o; o >>= 1) {
            float om = __shfl_xor_sync(0xffffffffu, mi, o);
            float os = __shfl_xor_sync(0xffffffffu, si, o);
            float mn = fmaxf(mi, om);
            si = si * __expf(mi - mn) + os * __expf(om - mn);
            mi = mn;
        }
        if (l == 0) {
            int b = b0 + r0 + i;
            float tl = g_tl[b] - g_tlq[b];
            float mn = fmaxf(mi, tl);
            float st = si * __expf(mi - mn) + __expf(tl - mn);
            out[b] = mn + xla_logf(st) - tl;
        }
    }
}

extern "C" void kernel_launch(void* const* d_in, const int* in_sizes, int n_in,
                              void* d_out, int out_size)
{
    const float* item = (const float*)d_in[0];   // [64, 1000000]
    const float* user = (const float*)d_in[1];   // [64, 4096]
    const int*   lab  = (const int*)  d_in[2];   // [4096, 1]
    const int*   sid  = (const int*)  d_in[3];   // [1024]
    float*       out  = (float*)d_out;           // [4096, 1]

    cudaFuncSetAttribute(fused_kernel,
                         cudaFuncAttributeMaxDynamicSharedMemorySize, 65536);

    prep_kernel<<<768, 256>>>(item, user, lab, sid);
    fused_kernel<<<BATCHN / RPB, 256, 65536>>>(user, lab, sid, out);
}